// round 5
// baseline (speedup 1.0000x reference)
#include <cuda_runtime.h>
#include <math.h>

#define N0 100000
#define N1 50000
#define N2 25000
#define N3 12500
#define D  128
#define EPAIR 10000
#define NTOT 87500          /* N1+N2+N3 */
#define ETOT 1125000        /* 750k+250k+125k */
#define BN_EPS 1e-5f

// ---------------- scratch ----------------
__device__ float g_xneg[N0 * D];
__device__ float g_bufA[2][N1 * D];
__device__ float g_bufB[2][N2 * D];
__device__ float g_agg [2][N1 * D];
__device__ int   g_cnt [NTOT];
__device__ int   g_off [NTOT + 1];
__device__ int   g_cur [NTOT];
__device__ int   g_csr [ETOT];
__device__ float g_stats[2][2][D];     // [stream][sum/sq][col]
__device__ float g_csum[D];
__device__ float g_csq_dummy[D];
__device__ float g_ws[D];
__device__ float g_loss[2];
__device__ float g_z [2 * EPAIR * D];
__device__ float g_z2[2 * EPAIR * D];

// ---------------- f32x2 helpers ----------------
__device__ __forceinline__ unsigned long long pk2(float x, float y) {
    unsigned long long r;
    asm("mov.b64 %0, {%1, %2};" : "=l"(r) : "f"(x), "f"(y));
    return r;
}
__device__ __forceinline__ void upk2(unsigned long long v, float& x, float& y) {
    asm("mov.b64 {%0, %1}, %2;" : "=f"(x), "=f"(y) : "l"(v));
}
__device__ __forceinline__ unsigned long long fma2(unsigned long long a,
                                                   unsigned long long b,
                                                   unsigned long long c) {
    unsigned long long d;
    asm("fma.rn.f32x2 %0, %1, %2, %3;" : "=l"(d) : "l"(a), "l"(b), "l"(c));
    return d;
}

// ---------------- misc kernels ----------------
__global__ void k_gather_perm(const float4* __restrict__ x, const int* __restrict__ perm,
                              float4* __restrict__ out) {
    int tid = blockIdx.x * blockDim.x + threadIdx.x;
    if (tid >= N0 * 32) return;
    int row = tid >> 5, q = tid & 31;
    out[row * 32 + q] = x[perm[row] * 32 + q];
}

// batched CSR: count / scan / fill over all 3 layers (global offset space)
__global__ void k_count_all(const int* __restrict__ d0, int E0,
                            const int* __restrict__ d1, int E1,
                            const int* __restrict__ d2, int E2,
                            int* __restrict__ cnt) {
    int e = blockIdx.x * blockDim.x + threadIdx.x;
    if (e < E0) atomicAdd(&cnt[d0[e]], 1);
    else if (e < E0 + E1) atomicAdd(&cnt[N1 + d1[e - E0]], 1);
    else if (e < E0 + E1 + E2) atomicAdd(&cnt[N1 + N2 + d2[e - E0 - E1]], 1);
}

__global__ void k_scan(const int* __restrict__ cnt, int n, int* __restrict__ off) {
    __shared__ int wsum[32];
    int t = threadIdx.x, lane = t & 31, wid = t >> 5;
    int carry = 0;
    for (int base = 0; base < n; base += 8192) {
        int v[8]; int s = 0;
#pragma unroll
        for (int u = 0; u < 8; u++) {
            int i = base + t * 8 + u;
            v[u] = (i < n) ? cnt[i] : 0;
            s += v[u];
        }
        int ps = s;
#pragma unroll
        for (int o = 1; o < 32; o <<= 1) {
            int x = __shfl_up_sync(0xffffffffu, ps, o);
            if (lane >= o) ps += x;
        }
        if (lane == 31) wsum[wid] = ps;
        __syncthreads();
        if (t < 32) {
            int x = wsum[t];
#pragma unroll
            for (int o = 1; o < 32; o <<= 1) {
                int y = __shfl_up_sync(0xffffffffu, x, o);
                if (t >= o) x += y;
            }
            wsum[t] = x;
        }
        __syncthreads();
        int warpbase = wid ? wsum[wid - 1] : 0;
        int run = carry + warpbase + (ps - s);
#pragma unroll
        for (int u = 0; u < 8; u++) {
            int i = base + t * 8 + u;
            if (i < n) off[i] = run;
            run += v[u];
        }
        carry += wsum[31];
        __syncthreads();
    }
    if (t == 0) off[n] = carry;
}

__global__ void k_fill_all(const int* __restrict__ s0, const int* __restrict__ d0, int E0,
                           const int* __restrict__ s1, const int* __restrict__ d1, int E1,
                           const int* __restrict__ s2, const int* __restrict__ d2, int E2,
                           const int* __restrict__ off, int* __restrict__ cur,
                           int* __restrict__ csr) {
    int e = blockIdx.x * blockDim.x + threadIdx.x;
    int src, node;
    if (e < E0) { src = s0[e]; node = d0[e]; }
    else if (e < E0 + E1) { int i = e - E0; src = s1[i]; node = N1 + d1[i]; }
    else if (e < E0 + E1 + E2) { int i = e - E0 - E1; src = s2[i]; node = N1 + N2 + d2[i]; }
    else return;
    int p = off[node] + atomicAdd(&cur[node], 1);
    csr[p] = src;
}

// one warp per dst row; neighbor mean for BOTH streams
__global__ void k_gather(const float4* __restrict__ hp, const float4* __restrict__ hn,
                         const int* __restrict__ csr, const int* __restrict__ off,
                         float4* __restrict__ ap, float4* __restrict__ an, int M) {
    int warp = (blockIdx.x * blockDim.x + threadIdx.x) >> 5;
    if (warp >= M) return;
    int lane = threadIdx.x & 31;
    int s0 = off[warp], s1 = off[warp + 1];
    float4 accp = make_float4(0.f, 0.f, 0.f, 0.f);
    float4 accn = make_float4(0.f, 0.f, 0.f, 0.f);
    int j = s0;
    for (; j + 2 <= s1; j += 2) {
        int sa = __ldg(&csr[j]), sb = __ldg(&csr[j + 1]);
        float4 v0 = hp[sa * 32 + lane];
        float4 v1 = hn[sa * 32 + lane];
        float4 w0 = hp[sb * 32 + lane];
        float4 w1 = hn[sb * 32 + lane];
        accp.x += v0.x + w0.x; accp.y += v0.y + w0.y;
        accp.z += v0.z + w0.z; accp.w += v0.w + w0.w;
        accn.x += v1.x + w1.x; accn.y += v1.y + w1.y;
        accn.z += v1.z + w1.z; accn.w += v1.w + w1.w;
    }
    if (j < s1) {
        int sa = __ldg(&csr[j]);
        float4 v0 = hp[sa * 32 + lane];
        float4 v1 = hn[sa * 32 + lane];
        accp.x += v0.x; accp.y += v0.y; accp.z += v0.z; accp.w += v0.w;
        accn.x += v1.x; accn.y += v1.y; accn.z += v1.z; accn.w += v1.w;
    }
    int deg = s1 - s0;
    float inv = 1.0f / (float)(deg > 0 ? deg : 1);
    accp.x *= inv; accp.y *= inv; accp.z *= inv; accp.w *= inv;
    accn.x *= inv; accn.y *= inv; accn.z *= inv; accn.w *= inv;
    ap[warp * 32 + lane] = accp;
    an[warp * 32 + lane] = accn;
}

// Fused dual-phase GEMM: C = A1@W1 [+ A2@W2] + b, optional relu, optional BN-stat
// epilogue, optional pair-product A gather (predictor), both streams via gridDim.y.
__global__ void gemm_dual(
    const float4* __restrict__ A1p, const float4* __restrict__ A1n,
    const float4* __restrict__ A2p, const float4* __restrict__ A2n,
    const float4* __restrict__ W1, const float4* __restrict__ W2,
    const float* __restrict__ bias,
    float4* __restrict__ Cp, float4* __restrict__ Cn,
    float* __restrict__ statsP, float* __restrict__ statsN,
    const int* __restrict__ ga, const int* __restrict__ gb,
    const int* __restrict__ ga2, const int* __restrict__ gb2,
    int M, int relu) {
    extern __shared__ float4 smem[];
    float4* sA = smem;          // [64][32]  32KB
    float4* sB = smem + 2048;   // [128][32] 64KB
    int t = threadIdx.x;
    int strm = blockIdx.y;
    int rowBase = blockIdx.x * 64;

    const float4* A1 = strm ? A1n : A1p;
    const float4* A2 = strm ? A2n : A2p;
    float4* C = strm ? Cn : Cp;
    float* stats = strm ? statsN : statsP;

    int c8 = t & 15;
    int r0 = (t >> 4) * 4;
    const ulonglong2* sB2 = (const ulonglong2*)sB;

    unsigned long long acc[4][4];
#pragma unroll
    for (int i = 0; i < 4; i++)
#pragma unroll
        for (int j = 0; j < 4; j++) acc[i][j] = 0ULL;

    int nphase = (A2p != nullptr) ? 2 : 1;
    for (int ph = 0; ph < nphase; ph++) {
        if (ph) __syncthreads();
        const float4* W = ph ? W2 : W1;
        const float4* A = ph ? A2 : A1;
#pragma unroll
        for (int i = 0; i < 16; i++) sB[t + i * 256] = W[t + i * 256];
#pragma unroll
        for (int i = 0; i < 8; i++) {
            int p = t + i * 256;
            int r = p >> 5, kq = p & 31;
            int row = rowBase + r;
            float4 v = make_float4(0.f, 0.f, 0.f, 0.f);
            if (row < M) {
                if (ga) {
                    const int* A_ = (row < EPAIR) ? ga : ga2;
                    const int* B_ = (row < EPAIR) ? gb : gb2;
                    int rr = (row < EPAIR) ? row : row - EPAIR;
                    float4 u = A[A_[rr] * 32 + kq];
                    float4 w = A[B_[rr] * 32 + kq];
                    v = make_float4(u.x * w.x, u.y * w.y, u.z * w.z, u.w * w.w);
                } else {
                    v = A[row * 32 + kq];
                }
            }
            sA[r * 32 + kq] = v;
        }
        __syncthreads();

#pragma unroll 4
        for (int k4 = 0; k4 < 32; k4++) {
            float4 a0 = sA[(r0 + 0) * 32 + k4];
            float4 a1 = sA[(r0 + 1) * 32 + k4];
            float4 a2 = sA[(r0 + 2) * 32 + k4];
            float4 a3 = sA[(r0 + 3) * 32 + k4];
#pragma unroll
            for (int kk = 0; kk < 4; kk++) {
                int k = k4 * 4 + kk;
                ulonglong2 p0 = sB2[k * 32 + c8 * 2];
                ulonglong2 p1 = sB2[k * 32 + c8 * 2 + 1];
                float f0 = kk == 0 ? a0.x : kk == 1 ? a0.y : kk == 2 ? a0.z : a0.w;
                float f1 = kk == 0 ? a1.x : kk == 1 ? a1.y : kk == 2 ? a1.z : a1.w;
                float f2 = kk == 0 ? a2.x : kk == 1 ? a2.y : kk == 2 ? a2.z : a2.w;
                float f3 = kk == 0 ? a3.x : kk == 1 ? a3.y : kk == 2 ? a3.z : a3.w;
                unsigned long long aa0 = pk2(f0, f0);
                unsigned long long aa1 = pk2(f1, f1);
                unsigned long long aa2 = pk2(f2, f2);
                unsigned long long aa3 = pk2(f3, f3);
                acc[0][0] = fma2(aa0, p0.x, acc[0][0]);
                acc[0][1] = fma2(aa0, p0.y, acc[0][1]);
                acc[0][2] = fma2(aa0, p1.x, acc[0][2]);
                acc[0][3] = fma2(aa0, p1.y, acc[0][3]);
                acc[1][0] = fma2(aa1, p0.x, acc[1][0]);
                acc[1][1] = fma2(aa1, p0.y, acc[1][1]);
                acc[1][2] = fma2(aa1, p1.x, acc[1][2]);
                acc[1][3] = fma2(aa1, p1.y, acc[1][3]);
                acc[2][0] = fma2(aa2, p0.x, acc[2][0]);
                acc[2][1] = fma2(aa2, p0.y, acc[2][1]);
                acc[2][2] = fma2(aa2, p1.x, acc[2][2]);
                acc[2][3] = fma2(aa2, p1.y, acc[2][3]);
                acc[3][0] = fma2(aa3, p0.x, acc[3][0]);
                acc[3][1] = fma2(aa3, p0.y, acc[3][1]);
                acc[3][2] = fma2(aa3, p1.x, acc[3][2]);
                acc[3][3] = fma2(aa3, p1.y, acc[3][3]);
            }
        }
    }

    float4 bv0 = make_float4(0.f, 0.f, 0.f, 0.f);
    float4 bv1 = make_float4(0.f, 0.f, 0.f, 0.f);
    if (bias) {
        bv0 = ((const float4*)bias)[c8 * 2];
        bv1 = ((const float4*)bias)[c8 * 2 + 1];
    }

    float csum[8] = {0, 0, 0, 0, 0, 0, 0, 0};
    float csq [8] = {0, 0, 0, 0, 0, 0, 0, 0};

#pragma unroll
    for (int i = 0; i < 4; i++) {
        int row = rowBase + r0 + i;
        if (row >= M) continue;
        float4 o0, o1;
        upk2(acc[i][0], o0.x, o0.y);
        upk2(acc[i][1], o0.z, o0.w);
        upk2(acc[i][2], o1.x, o1.y);
        upk2(acc[i][3], o1.z, o1.w);
        o0.x += bv0.x; o0.y += bv0.y; o0.z += bv0.z; o0.w += bv0.w;
        o1.x += bv1.x; o1.y += bv1.y; o1.z += bv1.z; o1.w += bv1.w;
        if (relu) {
            o0.x = fmaxf(o0.x, 0.f); o0.y = fmaxf(o0.y, 0.f);
            o0.z = fmaxf(o0.z, 0.f); o0.w = fmaxf(o0.w, 0.f);
            o1.x = fmaxf(o1.x, 0.f); o1.y = fmaxf(o1.y, 0.f);
            o1.z = fmaxf(o1.z, 0.f); o1.w = fmaxf(o1.w, 0.f);
        }
        csum[0] += o0.x; csq[0] += o0.x * o0.x;
        csum[1] += o0.y; csq[1] += o0.y * o0.y;
        csum[2] += o0.z; csq[2] += o0.z * o0.z;
        csum[3] += o0.w; csq[3] += o0.w * o0.w;
        csum[4] += o1.x; csq[4] += o1.x * o1.x;
        csum[5] += o1.y; csq[5] += o1.y * o1.y;
        csum[6] += o1.z; csq[6] += o1.z * o1.z;
        csum[7] += o1.w; csq[7] += o1.w * o1.w;
        C[row * 32 + c8 * 2]     = o0;
        C[row * 32 + c8 * 2 + 1] = o1;
    }

    if (stats) {
        int lane = t & 31;
#pragma unroll
        for (int j = 0; j < 8; j++) {
            csum[j] += __shfl_xor_sync(0xffffffffu, csum[j], 16);
            csq [j] += __shfl_xor_sync(0xffffffffu, csq [j], 16);
        }
        if (lane < 16) {
#pragma unroll
            for (int j = 0; j < 8; j++) {
                atomicAdd(&stats[c8 * 8 + j],       csum[j]);
                atomicAdd(&stats[D + c8 * 8 + j],   csq [j]);
            }
        }
    }
}

__global__ void k_bnrelu2(float* __restrict__ Hp, float* __restrict__ Hn,
                          const float* __restrict__ statsP, const float* __restrict__ statsN,
                          const float* __restrict__ gamma, const float* __restrict__ beta,
                          int M) {
    int idx = blockIdx.x * blockDim.x + threadIdx.x;
    int tot = M * D;
    if (idx >= 2 * tot) return;
    int strm = idx >= tot;
    int i = idx - strm * tot;
    float* H = strm ? Hn : Hp;
    const float* st = strm ? statsN : statsP;
    int c = i & 127;
    float invM = 1.0f / (float)M;
    float m = st[c] * invM;
    float v = st[D + c] * invM - m * m;
    float y = gamma[c] * (H[i] - m) * rsqrtf(v + BN_EPS) + beta[c];
    H[i] = fmaxf(y, 0.f);
}

__global__ void k_colstats(const float* __restrict__ H, int M,
                           float* __restrict__ sum, float* __restrict__ sq) {
    int c = threadIdx.x;
    int r0 = blockIdx.x * 256;
    int rend = r0 + 256; if (rend > M) rend = M;
    float s = 0.f, s2 = 0.f;
    for (int r = r0; r < rend; r++) {
        float v = H[r * D + c];
        s += v; s2 += v * v;
    }
    atomicAdd(&sum[c], s);
    atomicAdd(&sq[c], s2);
}

__global__ void k_summary_ws(const float* __restrict__ colsum,
                             const float* __restrict__ discW, float* __restrict__ ws) {
    __shared__ float sm[D];
    int t = threadIdx.x;
    float mn = colsum[t] / (float)N3;
    sm[t] = 1.0f / (1.0f + expf(-mn));
    __syncthreads();
    float a = 0.f;
#pragma unroll 8
    for (int j = 0; j < D; j++) a += discW[t * D + j] * sm[j];
    ws[t] = a;
}

__device__ __forceinline__ float warp_dot128(const float4* __restrict__ a,
                                             const float4* __restrict__ b, int lane) {
    float4 x = a[lane], y = b[lane];
    float s = x.x * y.x + x.y * y.y + x.z * y.z + x.w * y.w;
#pragma unroll
    for (int o = 16; o; o >>= 1) s += __shfl_down_sync(0xffffffffu, s, o);
    return s;
}

__global__ void k_loss(const float4* __restrict__ pos, const float4* __restrict__ neg,
                       const float4* __restrict__ ws, float* __restrict__ loss) {
    int tid = blockIdx.x * blockDim.x + threadIdx.x;
    int e = tid >> 5;
    if (e >= 2 * N3) return;
    int lane = tid & 31;
    int strm = (e >= N3);
    int r = e - strm * N3;
    const float4* row = (strm ? neg : pos) + r * 32;
    float s = warp_dot128(row, ws, lane);
    if (lane == 0) {
        float xx = strm ? s : -s;
        float sp = fmaxf(xx, 0.f) + log1pf(expf(-fabsf(xx)));
        atomicAdd(&loss[strm], sp);
    }
}

__global__ void k_pred_out(const float4* __restrict__ z, const float4* __restrict__ w3,
                           const float* __restrict__ b3, float* __restrict__ out) {
    int tid = blockIdx.x * blockDim.x + threadIdx.x;
    int e = tid >> 5;
    if (e >= 2 * EPAIR) return;
    int lane = tid & 31;
    float s = warp_dot128(z + e * 32, w3, lane);
    if (lane == 0) out[e] = s + b3[0];
}

__global__ void k_final_loss(const float* __restrict__ loss, float* __restrict__ out) {
    out[0] = (loss[0] + loss[1]) * (1.0f / (float)N3);
}

// ---------------- host orchestration ----------------
extern "C" void kernel_launch(void* const* d_in, const int* in_sizes, int n_in,
                              void* d_out, int out_size) {
    const float* x      = (const float*)d_in[0];
    const int* srcs[3]  = {(const int*)d_in[1], (const int*)d_in[3], (const int*)d_in[5]};
    const int* dsts[3]  = {(const int*)d_in[2], (const int*)d_in[4], (const int*)d_in[6]};
    const int* perm     = (const int*)d_in[7];
    const int* pos_src  = (const int*)d_in[8];
    const int* pos_dst  = (const int*)d_in[9];
    const int* neg_src  = (const int*)d_in[10];
    const int* neg_dst  = (const int*)d_in[11];
    const float* Ws[3]  = {(const float*)d_in[12], (const float*)d_in[15], (const float*)d_in[18]};
    const float* Wn[3]  = {(const float*)d_in[13], (const float*)d_in[16], (const float*)d_in[19]};
    const float* bb[3]  = {(const float*)d_in[14], (const float*)d_in[17], (const float*)d_in[20]};
    const float* gamma[2] = {(const float*)d_in[21], (const float*)d_in[23]};
    const float* beta [2] = {(const float*)d_in[22], (const float*)d_in[24]};
    const float* discW  = (const float*)d_in[25];
    const float* pW1 = (const float*)d_in[26]; const float* pb1 = (const float*)d_in[27];
    const float* pW2 = (const float*)d_in[28]; const float* pb2 = (const float*)d_in[29];
    const float* pW3 = (const float*)d_in[30]; const float* pb3 = (const float*)d_in[31];
    float* out = (float*)d_out;

    int E[3] = {in_sizes[1], in_sizes[3], in_sizes[5]};
    int ND[3] = {N1, N2, N3};
    int segbase[3] = {0, N1, N1 + N2};

    float *p_xneg, *p_bufA, *p_bufB, *p_agg, *p_stats, *p_csum, *p_csq,
          *p_ws, *p_loss, *p_z, *p_z2;
    int *p_cnt, *p_off, *p_cur, *p_csr;
    cudaGetSymbolAddress((void**)&p_xneg,  g_xneg);
    cudaGetSymbolAddress((void**)&p_bufA,  g_bufA);
    cudaGetSymbolAddress((void**)&p_bufB,  g_bufB);
    cudaGetSymbolAddress((void**)&p_agg,   g_agg);
    cudaGetSymbolAddress((void**)&p_cnt,   g_cnt);
    cudaGetSymbolAddress((void**)&p_off,   g_off);
    cudaGetSymbolAddress((void**)&p_cur,   g_cur);
    cudaGetSymbolAddress((void**)&p_csr,   g_csr);
    cudaGetSymbolAddress((void**)&p_stats, g_stats);
    cudaGetSymbolAddress((void**)&p_csum,  g_csum);
    cudaGetSymbolAddress((void**)&p_csq,   g_csq_dummy);
    cudaGetSymbolAddress((void**)&p_ws,    g_ws);
    cudaGetSymbolAddress((void**)&p_loss,  g_loss);
    cudaGetSymbolAddress((void**)&p_z,     g_z);
    cudaGetSymbolAddress((void**)&p_z2,    g_z2);

    cudaFuncSetAttribute(gemm_dual, cudaFuncAttributeMaxDynamicSharedMemorySize, 98304);
    const size_t GEMM_SMEM = 98304;

    int Etot = E[0] + E[1] + E[2];

    // negative-stream features
    k_gather_perm<<<(N0 * 32 + 255) / 256, 256>>>((const float4*)x, perm, (float4*)p_xneg);

    // batched CSR build (all 3 layers)
    cudaMemsetAsync(p_cnt, 0, NTOT * sizeof(int), 0);
    cudaMemsetAsync(p_cur, 0, NTOT * sizeof(int), 0);
    k_count_all<<<(Etot + 255) / 256, 256>>>(dsts[0], E[0], dsts[1], E[1], dsts[2], E[2], p_cnt);
    k_scan<<<1, 1024>>>(p_cnt, NTOT, p_off);
    k_fill_all<<<(Etot + 255) / 256, 256>>>(srcs[0], dsts[0], E[0],
                                            srcs[1], dsts[1], E[1],
                                            srcs[2], dsts[2], E[2],
                                            p_off, p_cur, p_csr);

    const float* hin[2] = {x, p_xneg};
    float* bufA[2] = {p_bufA, p_bufA + (size_t)N1 * D};
    float* bufB[2] = {p_bufB, p_bufB + (size_t)N2 * D};
    float* agg[2]  = {p_agg,  p_agg  + (size_t)N1 * D};
    float* stP = p_stats;            // [2*D]
    float* stN = p_stats + 2 * D;    // [2*D]

    for (int l = 0; l < 3; l++) {
        int nd = ND[l];
        float* outb[2];
        if (l == 1) { outb[0] = bufB[0]; outb[1] = bufB[1]; }
        else        { outb[0] = bufA[0]; outb[1] = bufA[1]; }

        k_gather<<<(nd * 32 + 255) / 256, 256>>>(
            (const float4*)hin[0], (const float4*)hin[1], p_csr, p_off + segbase[l],
            (float4*)agg[0], (float4*)agg[1], nd);

        bool bn = (l < 2);
        if (bn) cudaMemsetAsync(p_stats, 0, 2 * 2 * D * sizeof(float), 0);

        dim3 grid((nd + 63) / 64, 2);
        gemm_dual<<<grid, 256, GEMM_SMEM>>>(
            (const float4*)hin[0], (const float4*)hin[1],
            (const float4*)agg[0], (const float4*)agg[1],
            (const float4*)Ws[l], (const float4*)Wn[l], bb[l],
            (float4*)outb[0], (float4*)outb[1],
            bn ? stP : nullptr, bn ? stN : nullptr,
            nullptr, nullptr, nullptr, nullptr, nd, 0);

        if (bn)
            k_bnrelu2<<<(2 * nd * D + 255) / 256, 256>>>(outb[0], outb[1], stP, stN,
                                                         gamma[l], beta[l], nd);
        hin[0] = outb[0];
        hin[1] = outb[1];
    }

    float* positive = bufA[0];
    float* negative = bufA[1];

    cudaMemsetAsync(p_csum, 0, D * sizeof(float), 0);
    cudaMemsetAsync(p_loss, 0, 2 * sizeof(float), 0);
    k_colstats<<<(N3 + 255) / 256, 128>>>(positive, N3, p_csum, p_csq);
    k_summary_ws<<<1, 128>>>(p_csum, discW, p_ws);
    k_loss<<<(2 * N3 * 32 + 255) / 256, 256>>>((const float4*)positive,
                                               (const float4*)negative,
                                               (const float4*)p_ws, p_loss);

    // link predictor: 20000 rows (pos then neg), pair-product fused into GEMM1
    int Mp = 2 * EPAIR;
    dim3 pgrid((Mp + 63) / 64, 1);
    gemm_dual<<<pgrid, 256, GEMM_SMEM>>>(
        (const float4*)positive, (const float4*)positive,
        nullptr, nullptr,
        (const float4*)pW1, nullptr, pb1,
        (float4*)p_z2, (float4*)p_z2, nullptr, nullptr,
        pos_src, pos_dst, neg_src, neg_dst, Mp, 1);
    gemm_dual<<<pgrid, 256, GEMM_SMEM>>>(
        (const float4*)p_z2, (const float4*)p_z2,
        nullptr, nullptr,
        (const float4*)pW2, nullptr, pb2,
        (float4*)p_z, (float4*)p_z, nullptr, nullptr,
        nullptr, nullptr, nullptr, nullptr, Mp, 1);
    k_pred_out<<<(Mp * 32 + 255) / 256, 256>>>((const float4*)p_z,
                                               (const float4*)pW3, pb3, out);

    k_final_loss<<<1, 1>>>(p_loss, out + 2 * EPAIR);
}

// round 6
// speedup vs baseline: 2.0324x; 2.0324x over previous
#include <cuda_runtime.h>
#include <math.h>

#define N0 100000
#define N1 50000
#define N2 25000
#define N3 12500
#define D  128
#define EPAIR 10000
#define NTOT 87500          /* N1+N2+N3 */
#define ETOT 1125000
#define BN_EPS 1e-5f

// ---------------- scratch ----------------
__device__ float g_xneg[N0 * D];
__device__ float g_bufA[2][N1 * D];
__device__ float g_bufB[2][N2 * D];
__device__ float g_agg [2][N1 * D];
__device__ int   g_cnt [NTOT];
__device__ int   g_off [NTOT + 1];
__device__ int   g_cur [NTOT];
__device__ int   g_csr [ETOT];
__device__ float g_stats[2][2][D];
__device__ float g_csum[D];
__device__ float g_csq_dummy[D];
__device__ float g_ws[D];
__device__ float g_loss[2];
__device__ float g_z [2 * EPAIR * D];
__device__ float g_z2[2 * EPAIR * D];

// ---------------- f32x2 helpers ----------------
__device__ __forceinline__ unsigned long long pk2(float x, float y) {
    unsigned long long r;
    asm("mov.b64 %0, {%1, %2};" : "=l"(r) : "f"(x), "f"(y));
    return r;
}
__device__ __forceinline__ void upk2(unsigned long long v, float& x, float& y) {
    asm("mov.b64 {%0, %1}, %2;" : "=f"(x), "=f"(y) : "l"(v));
}
__device__ __forceinline__ unsigned long long fma2(unsigned long long a,
                                                   unsigned long long b,
                                                   unsigned long long c) {
    unsigned long long d;
    asm("fma.rn.f32x2 %0, %1, %2, %3;" : "=l"(d) : "l"(a), "l"(b), "l"(c));
    return d;
}

// ---------------- misc kernels ----------------
__global__ void k_gather_perm(const float4* __restrict__ x, const int* __restrict__ perm,
                              float4* __restrict__ out) {
    int tid = blockIdx.x * blockDim.x + threadIdx.x;
    if (tid >= N0 * 32) return;
    int row = tid >> 5, q = tid & 31;
    out[row * 32 + q] = x[perm[row] * 32 + q];
}

// batched CSR build over all 3 layers (global offset space)
__global__ void k_count_all(const int* __restrict__ d0, int E0,
                            const int* __restrict__ d1, int E1,
                            const int* __restrict__ d2, int E2,
                            int* __restrict__ cnt) {
    int e = blockIdx.x * blockDim.x + threadIdx.x;
    if (e < E0) atomicAdd(&cnt[d0[e]], 1);
    else if (e < E0 + E1) atomicAdd(&cnt[N1 + d1[e - E0]], 1);
    else if (e < E0 + E1 + E2) atomicAdd(&cnt[N1 + N2 + d2[e - E0 - E1]], 1);
}

__global__ void k_scan(const int* __restrict__ cnt, int n, int* __restrict__ off) {
    __shared__ int wsum[32];
    int t = threadIdx.x, lane = t & 31, wid = t >> 5;
    int carry = 0;
    for (int base = 0; base < n; base += 8192) {
        int v[8]; int s = 0;
#pragma unroll
        for (int u = 0; u < 8; u++) {
            int i = base + t * 8 + u;
            v[u] = (i < n) ? cnt[i] : 0;
            s += v[u];
        }
        int ps = s;
#pragma unroll
        for (int o = 1; o < 32; o <<= 1) {
            int x = __shfl_up_sync(0xffffffffu, ps, o);
            if (lane >= o) ps += x;
        }
        if (lane == 31) wsum[wid] = ps;
        __syncthreads();
        if (t < 32) {
            int x = wsum[t];
#pragma unroll
            for (int o = 1; o < 32; o <<= 1) {
                int y = __shfl_up_sync(0xffffffffu, x, o);
                if (t >= o) x += y;
            }
            wsum[t] = x;
        }
        __syncthreads();
        int warpbase = wid ? wsum[wid - 1] : 0;
        int run = carry + warpbase + (ps - s);
#pragma unroll
        for (int u = 0; u < 8; u++) {
            int i = base + t * 8 + u;
            if (i < n) off[i] = run;
            run += v[u];
        }
        carry += wsum[31];
        __syncthreads();
    }
    if (t == 0) off[n] = carry;
}

__global__ void k_fill_all(const int* __restrict__ s0, const int* __restrict__ d0, int E0,
                           const int* __restrict__ s1, const int* __restrict__ d1, int E1,
                           const int* __restrict__ s2, const int* __restrict__ d2, int E2,
                           const int* __restrict__ off, int* __restrict__ cur,
                           int* __restrict__ csr) {
    int e = blockIdx.x * blockDim.x + threadIdx.x;
    int src, node;
    if (e < E0) { src = s0[e]; node = d0[e]; }
    else if (e < E0 + E1) { int i = e - E0; src = s1[i]; node = N1 + d1[i]; }
    else if (e < E0 + E1 + E2) { int i = e - E0 - E1; src = s2[i]; node = N1 + N2 + d2[i]; }
    else return;
    int p = off[node] + atomicAdd(&cur[node], 1);
    csr[p] = src;
}

// one warp per dst row; neighbor mean for BOTH streams
__global__ void k_gather(const float4* __restrict__ hp, const float4* __restrict__ hn,
                         const int* __restrict__ csr, const int* __restrict__ off,
                         float4* __restrict__ ap, float4* __restrict__ an, int M) {
    int warp = (blockIdx.x * blockDim.x + threadIdx.x) >> 5;
    if (warp >= M) return;
    int lane = threadIdx.x & 31;
    int s0 = off[warp], s1 = off[warp + 1];
    float4 accp = make_float4(0.f, 0.f, 0.f, 0.f);
    float4 accn = make_float4(0.f, 0.f, 0.f, 0.f);
    int j = s0;
    for (; j + 2 <= s1; j += 2) {
        int sa = __ldg(&csr[j]), sb = __ldg(&csr[j + 1]);
        float4 v0 = hp[sa * 32 + lane];
        float4 v1 = hn[sa * 32 + lane];
        float4 w0 = hp[sb * 32 + lane];
        float4 w1 = hn[sb * 32 + lane];
        accp.x += v0.x + w0.x; accp.y += v0.y + w0.y;
        accp.z += v0.z + w0.z; accp.w += v0.w + w0.w;
        accn.x += v1.x + w1.x; accn.y += v1.y + w1.y;
        accn.z += v1.z + w1.z; accn.w += v1.w + w1.w;
    }
    if (j < s1) {
        int sa = __ldg(&csr[j]);
        float4 v0 = hp[sa * 32 + lane];
        float4 v1 = hn[sa * 32 + lane];
        accp.x += v0.x; accp.y += v0.y; accp.z += v0.z; accp.w += v0.w;
        accn.x += v1.x; accn.y += v1.y; accn.z += v1.z; accn.w += v1.w;
    }
    int deg = s1 - s0;
    float inv = 1.0f / (float)(deg > 0 ? deg : 1);
    accp.x *= inv; accp.y *= inv; accp.z *= inv; accp.w *= inv;
    accn.x *= inv; accn.y *= inv; accn.z *= inv; accn.w *= inv;
    ap[warp * 32 + lane] = accp;
    an[warp * 32 + lane] = accn;
}

// C[M,128] = A[M,128] @ W[128,128] (+bias)(+=C)(relu) — f32x2 inner loop.
// GATHER: A row = h[ga[r]] * h[gb[r]] (pair product, predictor layer 1;
//         rows >= EPAIR use ga2/gb2).
// flags: bit0 = accumulate into C, bit1 = relu
template <bool GATHER>
__global__ void __launch_bounds__(256, 1)
gemm128_t(const float4* __restrict__ A, const float4* __restrict__ W,
          const float* __restrict__ bias, float4* __restrict__ C,
          const int* __restrict__ ga, const int* __restrict__ gb,
          const int* __restrict__ ga2, const int* __restrict__ gb2,
          int M, int flags) {
    extern __shared__ float4 smem[];
    float4* sA = smem;          // [64][32]
    float4* sB = smem + 2048;   // [128][32]

    int t = threadIdx.x;
    int rowBase = blockIdx.x * 64;

#pragma unroll
    for (int i = 0; i < 16; i++) sB[t + i * 256] = W[t + i * 256];
#pragma unroll
    for (int i = 0; i < 8; i++) {
        int p = t + i * 256;
        int r = p >> 5, kq = p & 31;
        int row = rowBase + r;
        float4 v = make_float4(0.f, 0.f, 0.f, 0.f);
        if (row < M) {
            if (GATHER) {
                const int* A_ = (row < EPAIR) ? ga : ga2;
                const int* B_ = (row < EPAIR) ? gb : gb2;
                int rr = (row < EPAIR) ? row : row - EPAIR;
                float4 u = A[A_[rr] * 32 + kq];
                float4 w = A[B_[rr] * 32 + kq];
                v = make_float4(u.x * w.x, u.y * w.y, u.z * w.z, u.w * w.w);
            } else {
                v = A[row * 32 + kq];
            }
        }
        sA[r * 32 + kq] = v;
    }
    __syncthreads();

    int c8 = t & 15;
    int r0 = (t >> 4) * 4;
    const ulonglong2* sB2 = (const ulonglong2*)sB;

    unsigned long long acc[4][4];
#pragma unroll
    for (int i = 0; i < 4; i++)
#pragma unroll
        for (int j = 0; j < 4; j++) acc[i][j] = 0ULL;

#pragma unroll 4
    for (int k4 = 0; k4 < 32; k4++) {
        float4 a0 = sA[(r0 + 0) * 32 + k4];
        float4 a1 = sA[(r0 + 1) * 32 + k4];
        float4 a2 = sA[(r0 + 2) * 32 + k4];
        float4 a3 = sA[(r0 + 3) * 32 + k4];
#pragma unroll
        for (int kk = 0; kk < 4; kk++) {
            int k = k4 * 4 + kk;
            ulonglong2 p0 = sB2[k * 32 + c8 * 2];
            ulonglong2 p1 = sB2[k * 32 + c8 * 2 + 1];
            float f0 = kk == 0 ? a0.x : kk == 1 ? a0.y : kk == 2 ? a0.z : a0.w;
            float f1 = kk == 0 ? a1.x : kk == 1 ? a1.y : kk == 2 ? a1.z : a1.w;
            float f2 = kk == 0 ? a2.x : kk == 1 ? a2.y : kk == 2 ? a2.z : a2.w;
            float f3 = kk == 0 ? a3.x : kk == 1 ? a3.y : kk == 2 ? a3.z : a3.w;
            unsigned long long aa0 = pk2(f0, f0);
            unsigned long long aa1 = pk2(f1, f1);
            unsigned long long aa2 = pk2(f2, f2);
            unsigned long long aa3 = pk2(f3, f3);
            acc[0][0] = fma2(aa0, p0.x, acc[0][0]);
            acc[0][1] = fma2(aa0, p0.y, acc[0][1]);
            acc[0][2] = fma2(aa0, p1.x, acc[0][2]);
            acc[0][3] = fma2(aa0, p1.y, acc[0][3]);
            acc[1][0] = fma2(aa1, p0.x, acc[1][0]);
            acc[1][1] = fma2(aa1, p0.y, acc[1][1]);
            acc[1][2] = fma2(aa1, p1.x, acc[1][2]);
            acc[1][3] = fma2(aa1, p1.y, acc[1][3]);
            acc[2][0] = fma2(aa2, p0.x, acc[2][0]);
            acc[2][1] = fma2(aa2, p0.y, acc[2][1]);
            acc[2][2] = fma2(aa2, p1.x, acc[2][2]);
            acc[2][3] = fma2(aa2, p1.y, acc[2][3]);
            acc[3][0] = fma2(aa3, p0.x, acc[3][0]);
            acc[3][1] = fma2(aa3, p0.y, acc[3][1]);
            acc[3][2] = fma2(aa3, p1.x, acc[3][2]);
            acc[3][3] = fma2(aa3, p1.y, acc[3][3]);
        }
    }

    float4 bv0 = make_float4(0.f, 0.f, 0.f, 0.f);
    float4 bv1 = make_float4(0.f, 0.f, 0.f, 0.f);
    if (bias) {
        bv0 = ((const float4*)bias)[c8 * 2];
        bv1 = ((const float4*)bias)[c8 * 2 + 1];
    }

#pragma unroll
    for (int i = 0; i < 4; i++) {
        int row = rowBase + r0 + i;
        if (row >= M) continue;
        float4 o0, o1;
        upk2(acc[i][0], o0.x, o0.y);
        upk2(acc[i][1], o0.z, o0.w);
        upk2(acc[i][2], o1.x, o1.y);
        upk2(acc[i][3], o1.z, o1.w);
        o0.x += bv0.x; o0.y += bv0.y; o0.z += bv0.z; o0.w += bv0.w;
        o1.x += bv1.x; o1.y += bv1.y; o1.z += bv1.z; o1.w += bv1.w;
        if (flags & 1) {
            float4 q0 = C[row * 32 + c8 * 2];
            float4 q1 = C[row * 32 + c8 * 2 + 1];
            o0.x += q0.x; o0.y += q0.y; o0.z += q0.z; o0.w += q0.w;
            o1.x += q1.x; o1.y += q1.y; o1.z += q1.z; o1.w += q1.w;
        }
        if (flags & 2) {
            o0.x = fmaxf(o0.x, 0.f); o0.y = fmaxf(o0.y, 0.f);
            o0.z = fmaxf(o0.z, 0.f); o0.w = fmaxf(o0.w, 0.f);
            o1.x = fmaxf(o1.x, 0.f); o1.y = fmaxf(o1.y, 0.f);
            o1.z = fmaxf(o1.z, 0.f); o1.w = fmaxf(o1.w, 0.f);
        }
        C[row * 32 + c8 * 2]     = o0;
        C[row * 32 + c8 * 2 + 1] = o1;
    }
}

__global__ void k_colstats(const float* __restrict__ H, int M,
                           float* __restrict__ sum, float* __restrict__ sq) {
    int c = threadIdx.x;
    int r0 = blockIdx.x * 256;
    int rend = r0 + 256; if (rend > M) rend = M;
    float s = 0.f, s2 = 0.f;
    for (int r = r0; r < rend; r++) {
        float v = H[r * D + c];
        s += v; s2 += v * v;
    }
    atomicAdd(&sum[c], s);
    atomicAdd(&sq[c], s2);
}

__global__ void k_bnrelu(float* __restrict__ H, const float* __restrict__ sum,
                         const float* __restrict__ sq, const float* __restrict__ gamma,
                         const float* __restrict__ beta, int M) {
    int idx = blockIdx.x * blockDim.x + threadIdx.x;
    if (idx >= M * D) return;
    int c = idx & 127;
    float invM = 1.0f / (float)M;
    float m = sum[c] * invM;
    float v = sq[c] * invM - m * m;
    float y = gamma[c] * (H[idx] - m) * rsqrtf(v + BN_EPS) + beta[c];
    H[idx] = fmaxf(y, 0.f);
}

__global__ void k_summary_ws(const float* __restrict__ colsum,
                             const float* __restrict__ discW, float* __restrict__ ws) {
    __shared__ float sm[D];
    int t = threadIdx.x;
    float mn = colsum[t] / (float)N3;
    sm[t] = 1.0f / (1.0f + expf(-mn));
    __syncthreads();
    float a = 0.f;
#pragma unroll 8
    for (int j = 0; j < D; j++) a += discW[t * D + j] * sm[j];
    ws[t] = a;
}

__device__ __forceinline__ float warp_dot128(const float4* __restrict__ a,
                                             const float4* __restrict__ b, int lane) {
    float4 x = a[lane], y = b[lane];
    float s = x.x * y.x + x.y * y.y + x.z * y.z + x.w * y.w;
#pragma unroll
    for (int o = 16; o; o >>= 1) s += __shfl_down_sync(0xffffffffu, s, o);
    return s;
}

__global__ void k_loss(const float4* __restrict__ pos, const float4* __restrict__ neg,
                       const float4* __restrict__ ws, float* __restrict__ loss) {
    int tid = blockIdx.x * blockDim.x + threadIdx.x;
    int e = tid >> 5;
    if (e >= 2 * N3) return;
    int lane = tid & 31;
    int strm = (e >= N3);
    int r = e - strm * N3;
    const float4* row = (strm ? neg : pos) + r * 32;
    float s = warp_dot128(row, ws, lane);
    if (lane == 0) {
        float xx = strm ? s : -s;
        float sp = fmaxf(xx, 0.f) + log1pf(expf(-fabsf(xx)));
        atomicAdd(&loss[strm], sp);
    }
}

__global__ void k_pred_out(const float4* __restrict__ z, const float4* __restrict__ w3,
                           const float* __restrict__ b3, float* __restrict__ out) {
    int tid = blockIdx.x * blockDim.x + threadIdx.x;
    int e = tid >> 5;
    if (e >= 2 * EPAIR) return;
    int lane = tid & 31;
    float s = warp_dot128(z + e * 32, w3, lane);
    if (lane == 0) out[e] = s + b3[0];
}

__global__ void k_final_loss(const float* __restrict__ loss, float* __restrict__ out) {
    out[0] = (loss[0] + loss[1]) * (1.0f / (float)N3);
}

// ---------------- host orchestration ----------------
extern "C" void kernel_launch(void* const* d_in, const int* in_sizes, int n_in,
                              void* d_out, int out_size) {
    const float* x      = (const float*)d_in[0];
    const int* srcs[3]  = {(const int*)d_in[1], (const int*)d_in[3], (const int*)d_in[5]};
    const int* dsts[3]  = {(const int*)d_in[2], (const int*)d_in[4], (const int*)d_in[6]};
    const int* perm     = (const int*)d_in[7];
    const int* pos_src  = (const int*)d_in[8];
    const int* pos_dst  = (const int*)d_in[9];
    const int* neg_src  = (const int*)d_in[10];
    const int* neg_dst  = (const int*)d_in[11];
    const float* Ws[3]  = {(const float*)d_in[12], (const float*)d_in[15], (const float*)d_in[18]};
    const float* Wn[3]  = {(const float*)d_in[13], (const float*)d_in[16], (const float*)d_in[19]};
    const float* bb[3]  = {(const float*)d_in[14], (const float*)d_in[17], (const float*)d_in[20]};
    const float* gamma[2] = {(const float*)d_in[21], (const float*)d_in[23]};
    const float* beta [2] = {(const float*)d_in[22], (const float*)d_in[24]};
    const float* discW  = (const float*)d_in[25];
    const float* pW1 = (const float*)d_in[26]; const float* pb1 = (const float*)d_in[27];
    const float* pW2 = (const float*)d_in[28]; const float* pb2 = (const float*)d_in[29];
    const float* pW3 = (const float*)d_in[30]; const float* pb3 = (const float*)d_in[31];
    float* out = (float*)d_out;

    int E[3] = {in_sizes[1], in_sizes[3], in_sizes[5]};
    int ND[3] = {N1, N2, N3};
    int segbase[3] = {0, N1, N1 + N2};

    float *p_xneg, *p_bufA, *p_bufB, *p_agg, *p_stats, *p_csum, *p_csq,
          *p_ws, *p_loss, *p_z, *p_z2;
    int *p_cnt, *p_off, *p_cur, *p_csr;
    cudaGetSymbolAddress((void**)&p_xneg,  g_xneg);
    cudaGetSymbolAddress((void**)&p_bufA,  g_bufA);
    cudaGetSymbolAddress((void**)&p_bufB,  g_bufB);
    cudaGetSymbolAddress((void**)&p_agg,   g_agg);
    cudaGetSymbolAddress((void**)&p_cnt,   g_cnt);
    cudaGetSymbolAddress((void**)&p_off,   g_off);
    cudaGetSymbolAddress((void**)&p_cur,   g_cur);
    cudaGetSymbolAddress((void**)&p_csr,   g_csr);
    cudaGetSymbolAddress((void**)&p_stats, g_stats);
    cudaGetSymbolAddress((void**)&p_csum,  g_csum);
    cudaGetSymbolAddress((void**)&p_csq,   g_csq_dummy);
    cudaGetSymbolAddress((void**)&p_ws,    g_ws);
    cudaGetSymbolAddress((void**)&p_loss,  g_loss);
    cudaGetSymbolAddress((void**)&p_z,     g_z);
    cudaGetSymbolAddress((void**)&p_z2,    g_z2);

    cudaFuncSetAttribute(gemm128_t<false>, cudaFuncAttributeMaxDynamicSharedMemorySize, 98304);
    cudaFuncSetAttribute(gemm128_t<true>,  cudaFuncAttributeMaxDynamicSharedMemorySize, 98304);
    const size_t GEMM_SMEM = 98304;

    int Etot = E[0] + E[1] + E[2];

    // negative-stream features
    k_gather_perm<<<(N0 * 32 + 255) / 256, 256>>>((const float4*)x, perm, (float4*)p_xneg);

    // batched CSR build (all 3 layers at once)
    cudaMemsetAsync(p_cnt, 0, NTOT * sizeof(int), 0);
    cudaMemsetAsync(p_cur, 0, NTOT * sizeof(int), 0);
    k_count_all<<<(Etot + 255) / 256, 256>>>(dsts[0], E[0], dsts[1], E[1], dsts[2], E[2], p_cnt);
    k_scan<<<1, 1024>>>(p_cnt, NTOT, p_off);
    k_fill_all<<<(Etot + 255) / 256, 256>>>(srcs[0], dsts[0], E[0],
                                            srcs[1], dsts[1], E[1],
                                            srcs[2], dsts[2], E[2],
                                            p_off, p_cur, p_csr);

    const float* hin[2] = {x, p_xneg};
    float* bufA[2] = {p_bufA, p_bufA + (size_t)N1 * D};
    float* bufB[2] = {p_bufB, p_bufB + (size_t)N2 * D};
    float* agg[2]  = {p_agg,  p_agg  + (size_t)N1 * D};

    for (int l = 0; l < 3; l++) {
        int nd = ND[l];
        float* outb[2];
        if (l == 1) { outb[0] = bufB[0]; outb[1] = bufB[1]; }
        else        { outb[0] = bufA[0]; outb[1] = bufA[1]; }

        k_gather<<<(nd * 32 + 255) / 256, 256>>>(
            (const float4*)hin[0], (const float4*)hin[1], p_csr, p_off + segbase[l],
            (float4*)agg[0], (float4*)agg[1], nd);

        int gblocks = (nd + 63) / 64;
        for (int s = 0; s < 2; s++) {
            gemm128_t<false><<<gblocks, 256, GEMM_SMEM>>>(
                (const float4*)hin[s], (const float4*)Ws[l], bb[l], (float4*)outb[s],
                nullptr, nullptr, nullptr, nullptr, nd, 0);
            gemm128_t<false><<<gblocks, 256, GEMM_SMEM>>>(
                (const float4*)agg[s], (const float4*)Wn[l], nullptr, (float4*)outb[s],
                nullptr, nullptr, nullptr, nullptr, nd, 1);
        }

        if (l < 2) {
            for (int s = 0; s < 2; s++) {
                float* st_sum = p_stats + s * 2 * D;
                float* st_sq  = st_sum + D;
                cudaMemsetAsync(st_sum, 0, 2 * D * sizeof(float), 0);
                k_colstats<<<(nd + 255) / 256, 128>>>(outb[s], nd, st_sum, st_sq);
                k_bnrelu<<<(nd * D + 255) / 256, 256>>>(outb[s], st_sum, st_sq,
                                                        gamma[l], beta[l], nd);
            }
        }
        hin[0] = outb[0];
        hin[1] = outb[1];
    }

    float* positive = bufA[0];
    float* negative = bufA[1];

    cudaMemsetAsync(p_csum, 0, D * sizeof(float), 0);
    cudaMemsetAsync(p_loss, 0, 2 * sizeof(float), 0);
    k_colstats<<<(N3 + 255) / 256, 128>>>(positive, N3, p_csum, p_csq);
    k_summary_ws<<<1, 128>>>(p_csum, discW, p_ws);
    k_loss<<<(2 * N3 * 32 + 255) / 256, 256>>>((const float4*)positive,
                                               (const float4*)negative,
                                               (const float4*)p_ws, p_loss);

    // link predictor: 20000 rows (pos then neg); pair-product fused into GEMM1
    int Mp = 2 * EPAIR;
    int pgblocks = (Mp + 63) / 64;
    gemm128_t<true><<<pgblocks, 256, GEMM_SMEM>>>(
        (const float4*)positive, (const float4*)pW1, pb1, (float4*)p_z2,
        pos_src, pos_dst, neg_src, neg_dst, Mp, 2);
    gemm128_t<false><<<pgblocks, 256, GEMM_SMEM>>>(
        (const float4*)p_z2, (const float4*)pW2, pb2, (float4*)p_z,
        nullptr, nullptr, nullptr, nullptr, Mp, 2);
    k_pred_out<<<(Mp * 32 + 255) / 256, 256>>>((const float4*)p_z,
                                               (const float4*)pW3, pb3, out);

    k_final_loss<<<1, 1>>>(p_loss, out + 2 * EPAIR);
}

// round 7
// speedup vs baseline: 2.6159x; 1.2871x over previous
#include <cuda_runtime.h>
#include <math.h>

#define N0 100000
#define N1 50000
#define N2 25000
#define N3 12500
#define D  128
#define EPAIR 10000
#define NTOT 87500
#define ETOT 1125000
#define BN_EPS 1e-5f

// ---------------- scratch ----------------
__device__ float g_xneg[N0 * D];
__device__ float g_bufA[2][N1 * D];
__device__ float g_bufB[2][N2 * D];
__device__ float g_agg [2][N1 * D];
__device__ int   g_cnt [NTOT];
__device__ int   g_off [NTOT + 1];
__device__ int   g_cur [NTOT];
__device__ int   g_csr [ETOT];
__device__ float g_stats[2][2][D];
__device__ float g_csum[D];
__device__ float g_csq_dummy[D];
__device__ float g_ws[D];
__device__ float g_loss[2];
__device__ float g_z [2 * EPAIR * D];
__device__ float g_z2[2 * EPAIR * D];

// ---------------- f32x2 helpers ----------------
__device__ __forceinline__ unsigned long long pk2(float x, float y) {
    unsigned long long r;
    asm("mov.b64 %0, {%1, %2};" : "=l"(r) : "f"(x), "f"(y));
    return r;
}
__device__ __forceinline__ void upk2(unsigned long long v, float& x, float& y) {
    asm("mov.b64 {%0, %1}, %2;" : "=f"(x), "=f"(y) : "l"(v));
}
__device__ __forceinline__ unsigned long long fma2(unsigned long long a,
                                                   unsigned long long b,
                                                   unsigned long long c) {
    unsigned long long d;
    asm("fma.rn.f32x2 %0, %1, %2, %3;" : "=l"(d) : "l"(a), "l"(b), "l"(c));
    return d;
}

// ---------------- misc kernels ----------------
__global__ void k_gather_perm(const float4* __restrict__ x, const int* __restrict__ perm,
                              float4* __restrict__ out) {
    int tid = blockIdx.x * blockDim.x + threadIdx.x;
    if (tid >= N0 * 32) return;
    int row = tid >> 5, q = tid & 31;
    out[row * 32 + q] = x[perm[row] * 32 + q];
}

__global__ void k_count_all(const int* __restrict__ d0, int E0,
                            const int* __restrict__ d1, int E1,
                            const int* __restrict__ d2, int E2,
                            int* __restrict__ cnt) {
    int e = blockIdx.x * blockDim.x + threadIdx.x;
    if (e < E0) atomicAdd(&cnt[d0[e]], 1);
    else if (e < E0 + E1) atomicAdd(&cnt[N1 + d1[e - E0]], 1);
    else if (e < E0 + E1 + E2) atomicAdd(&cnt[N1 + N2 + d2[e - E0 - E1]], 1);
}

__global__ void k_scan(const int* __restrict__ cnt, int n, int* __restrict__ off) {
    __shared__ int wsum[32];
    int t = threadIdx.x, lane = t & 31, wid = t >> 5;
    int carry = 0;
    for (int base = 0; base < n; base += 8192) {
        int v[8]; int s = 0;
#pragma unroll
        for (int u = 0; u < 8; u++) {
            int i = base + t * 8 + u;
            v[u] = (i < n) ? cnt[i] : 0;
            s += v[u];
        }
        int ps = s;
#pragma unroll
        for (int o = 1; o < 32; o <<= 1) {
            int x = __shfl_up_sync(0xffffffffu, ps, o);
            if (lane >= o) ps += x;
        }
        if (lane == 31) wsum[wid] = ps;
        __syncthreads();
        if (t < 32) {
            int x = wsum[t];
#pragma unroll
            for (int o = 1; o < 32; o <<= 1) {
                int y = __shfl_up_sync(0xffffffffu, x, o);
                if (t >= o) x += y;
            }
            wsum[t] = x;
        }
        __syncthreads();
        int warpbase = wid ? wsum[wid - 1] : 0;
        int run = carry + warpbase + (ps - s);
#pragma unroll
        for (int u = 0; u < 8; u++) {
            int i = base + t * 8 + u;
            if (i < n) off[i] = run;
            run += v[u];
        }
        carry += wsum[31];
        __syncthreads();
    }
    if (t == 0) off[n] = carry;
}

__global__ void k_fill_all(const int* __restrict__ s0, const int* __restrict__ d0, int E0,
                           const int* __restrict__ s1, const int* __restrict__ d1, int E1,
                           const int* __restrict__ s2, const int* __restrict__ d2, int E2,
                           const int* __restrict__ off, int* __restrict__ cur,
                           int* __restrict__ csr) {
    int e = blockIdx.x * blockDim.x + threadIdx.x;
    int src, node;
    if (e < E0) { src = s0[e]; node = d0[e]; }
    else if (e < E0 + E1) { int i = e - E0; src = s1[i]; node = N1 + d1[i]; }
    else if (e < E0 + E1 + E2) { int i = e - E0 - E1; src = s2[i]; node = N1 + N2 + d2[i]; }
    else return;
    int p = off[node] + atomicAdd(&cur[node], 1);
    csr[p] = src;
}

__global__ void k_gather(const float4* __restrict__ hp, const float4* __restrict__ hn,
                         const int* __restrict__ csr, const int* __restrict__ off,
                         float4* __restrict__ ap, float4* __restrict__ an, int M) {
    int warp = (blockIdx.x * blockDim.x + threadIdx.x) >> 5;
    if (warp >= M) return;
    int lane = threadIdx.x & 31;
    int s0 = off[warp], s1 = off[warp + 1];
    float4 accp = make_float4(0.f, 0.f, 0.f, 0.f);
    float4 accn = make_float4(0.f, 0.f, 0.f, 0.f);
    int j = s0;
    for (; j + 2 <= s1; j += 2) {
        int sa = __ldg(&csr[j]), sb = __ldg(&csr[j + 1]);
        float4 v0 = hp[sa * 32 + lane];
        float4 v1 = hn[sa * 32 + lane];
        float4 w0 = hp[sb * 32 + lane];
        float4 w1 = hn[sb * 32 + lane];
        accp.x += v0.x + w0.x; accp.y += v0.y + w0.y;
        accp.z += v0.z + w0.z; accp.w += v0.w + w0.w;
        accn.x += v1.x + w1.x; accn.y += v1.y + w1.y;
        accn.z += v1.z + w1.z; accn.w += v1.w + w1.w;
    }
    if (j < s1) {
        int sa = __ldg(&csr[j]);
        float4 v0 = hp[sa * 32 + lane];
        float4 v1 = hn[sa * 32 + lane];
        accp.x += v0.x; accp.y += v0.y; accp.z += v0.z; accp.w += v0.w;
        accn.x += v1.x; accn.y += v1.y; accn.z += v1.z; accn.w += v1.w;
    }
    int deg = s1 - s0;
    float inv = 1.0f / (float)(deg > 0 ? deg : 1);
    accp.x *= inv; accp.y *= inv; accp.z *= inv; accp.w *= inv;
    accn.x *= inv; accn.y *= inv; accn.z *= inv; accn.w *= inv;
    ap[warp * 32 + lane] = accp;
    an[warp * 32 + lane] = accn;
}

// C = A1@W1 [+ A2@W2] + bias, optional relu.
// 512 threads, 128-row tile, 4 rows x 8 cols per thread.
// Column map per thread: cols [4*c8, 4*c8+4) and [64+4*c8, 64+4*c8+4)
// (lane-contiguous B reads -> conflict-free LDS).
// Stream (pos/neg) selected by blockIdx.y.
template <bool DUAL, bool GATHER>
__global__ void __launch_bounds__(512, 1)
gemm128_v2(const float4* __restrict__ A1p, const float4* __restrict__ A1n,
           const float4* __restrict__ A2p, const float4* __restrict__ A2n,
           const float4* __restrict__ W1, const float4* __restrict__ W2,
           const float* __restrict__ bias,
           float4* __restrict__ Cp, float4* __restrict__ Cn,
           const int* __restrict__ ga, const int* __restrict__ gb,
           const int* __restrict__ ga2, const int* __restrict__ gb2,
           int M, int relu) {
    extern __shared__ float4 smem[];
    float4* sA = smem;          // [128][32] 64KB
    float4* sB = smem + 4096;   // [128][32] 64KB

    int t = threadIdx.x;
    int rowBase = blockIdx.x * 128;
    int strm = blockIdx.y;

    const float4* A1 = strm ? A1n : A1p;
    const float4* A2 = strm ? A2n : A2p;
    float4* C = strm ? Cn : Cp;

    int c8 = t & 15;
    int r0 = (t >> 4) * 4;
    const ulonglong2* sB2 = (const ulonglong2*)sB;

    unsigned long long acc[4][4];
#pragma unroll
    for (int i = 0; i < 4; i++)
#pragma unroll
        for (int j = 0; j < 4; j++) acc[i][j] = 0ULL;

#pragma unroll
    for (int ph = 0; ph < (DUAL ? 2 : 1); ph++) {
        if (ph) __syncthreads();
        const float4* W = ph ? W2 : W1;
        const float4* A = ph ? A2 : A1;
#pragma unroll
        for (int i = 0; i < 8; i++) sB[t + i * 512] = W[t + i * 512];
#pragma unroll
        for (int i = 0; i < 8; i++) {
            int p = t + i * 512;
            int r = p >> 5, kq = p & 31;
            int row = rowBase + r;
            float4 v = make_float4(0.f, 0.f, 0.f, 0.f);
            if (row < M) {
                if (GATHER) {
                    const int* A_ = (row < EPAIR) ? ga : ga2;
                    const int* B_ = (row < EPAIR) ? gb : gb2;
                    int rr = (row < EPAIR) ? row : row - EPAIR;
                    float4 u = A[A_[rr] * 32 + kq];
                    float4 w = A[B_[rr] * 32 + kq];
                    v = make_float4(u.x * w.x, u.y * w.y, u.z * w.z, u.w * w.w);
                } else {
                    v = A[row * 32 + kq];
                }
            }
            sA[r * 32 + kq] = v;
        }
        __syncthreads();

#pragma unroll 4
        for (int k4 = 0; k4 < 32; k4++) {
            float4 a0 = sA[(r0 + 0) * 32 + k4];
            float4 a1 = sA[(r0 + 1) * 32 + k4];
            float4 a2 = sA[(r0 + 2) * 32 + k4];
            float4 a3 = sA[(r0 + 3) * 32 + k4];
#pragma unroll
            for (int kk = 0; kk < 4; kk++) {
                int k = k4 * 4 + kk;
                ulonglong2 p0 = sB2[k * 32 + c8];        // cols 4c8..4c8+3
                ulonglong2 p1 = sB2[k * 32 + 16 + c8];   // cols 64+4c8..64+4c8+3
                float f0 = kk == 0 ? a0.x : kk == 1 ? a0.y : kk == 2 ? a0.z : a0.w;
                float f1 = kk == 0 ? a1.x : kk == 1 ? a1.y : kk == 2 ? a1.z : a1.w;
                float f2 = kk == 0 ? a2.x : kk == 1 ? a2.y : kk == 2 ? a2.z : a2.w;
                float f3 = kk == 0 ? a3.x : kk == 1 ? a3.y : kk == 2 ? a3.z : a3.w;
                unsigned long long aa0 = pk2(f0, f0);
                unsigned long long aa1 = pk2(f1, f1);
                unsigned long long aa2 = pk2(f2, f2);
                unsigned long long aa3 = pk2(f3, f3);
                acc[0][0] = fma2(aa0, p0.x, acc[0][0]);
                acc[0][1] = fma2(aa0, p0.y, acc[0][1]);
                acc[0][2] = fma2(aa0, p1.x, acc[0][2]);
                acc[0][3] = fma2(aa0, p1.y, acc[0][3]);
                acc[1][0] = fma2(aa1, p0.x, acc[1][0]);
                acc[1][1] = fma2(aa1, p0.y, acc[1][1]);
                acc[1][2] = fma2(aa1, p1.x, acc[1][2]);
                acc[1][3] = fma2(aa1, p1.y, acc[1][3]);
                acc[2][0] = fma2(aa2, p0.x, acc[2][0]);
                acc[2][1] = fma2(aa2, p0.y, acc[2][1]);
                acc[2][2] = fma2(aa2, p1.x, acc[2][2]);
                acc[2][3] = fma2(aa2, p1.y, acc[2][3]);
                acc[3][0] = fma2(aa3, p0.x, acc[3][0]);
                acc[3][1] = fma2(aa3, p0.y, acc[3][1]);
                acc[3][2] = fma2(aa3, p1.x, acc[3][2]);
                acc[3][3] = fma2(aa3, p1.y, acc[3][3]);
            }
        }
    }

    float4 bv0 = make_float4(0.f, 0.f, 0.f, 0.f);
    float4 bv1 = make_float4(0.f, 0.f, 0.f, 0.f);
    if (bias) {
        bv0 = ((const float4*)bias)[c8];
        bv1 = ((const float4*)bias)[16 + c8];
    }

#pragma unroll
    for (int i = 0; i < 4; i++) {
        int row = rowBase + r0 + i;
        if (row >= M) continue;
        float4 o0, o1;
        upk2(acc[i][0], o0.x, o0.y);
        upk2(acc[i][1], o0.z, o0.w);
        upk2(acc[i][2], o1.x, o1.y);
        upk2(acc[i][3], o1.z, o1.w);
        o0.x += bv0.x; o0.y += bv0.y; o0.z += bv0.z; o0.w += bv0.w;
        o1.x += bv1.x; o1.y += bv1.y; o1.z += bv1.z; o1.w += bv1.w;
        if (relu) {
            o0.x = fmaxf(o0.x, 0.f); o0.y = fmaxf(o0.y, 0.f);
            o0.z = fmaxf(o0.z, 0.f); o0.w = fmaxf(o0.w, 0.f);
            o1.x = fmaxf(o1.x, 0.f); o1.y = fmaxf(o1.y, 0.f);
            o1.z = fmaxf(o1.z, 0.f); o1.w = fmaxf(o1.w, 0.f);
        }
        C[row * 32 + c8]      = o0;
        C[row * 32 + 16 + c8] = o1;
    }
}

__global__ void k_colstats(const float* __restrict__ H, int M,
                           float* __restrict__ sum, float* __restrict__ sq) {
    int c = threadIdx.x;
    int r0 = blockIdx.x * 256;
    int rend = r0 + 256; if (rend > M) rend = M;
    float s = 0.f, s2 = 0.f;
    for (int r = r0; r < rend; r++) {
        float v = H[r * D + c];
        s += v; s2 += v * v;
    }
    atomicAdd(&sum[c], s);
    atomicAdd(&sq[c], s2);
}

__global__ void k_bnrelu(float* __restrict__ H, const float* __restrict__ sum,
                         const float* __restrict__ sq, const float* __restrict__ gamma,
                         const float* __restrict__ beta, int M) {
    int idx = blockIdx.x * blockDim.x + threadIdx.x;
    if (idx >= M * D) return;
    int c = idx & 127;
    float invM = 1.0f / (float)M;
    float m = sum[c] * invM;
    float v = sq[c] * invM - m * m;
    float y = gamma[c] * (H[idx] - m) * rsqrtf(v + BN_EPS) + beta[c];
    H[idx] = fmaxf(y, 0.f);
}

__global__ void k_summary_ws(const float* __restrict__ colsum,
                             const float* __restrict__ discW, float* __restrict__ ws) {
    __shared__ float sm[D];
    int t = threadIdx.x;
    float mn = colsum[t] / (float)N3;
    sm[t] = 1.0f / (1.0f + expf(-mn));
    __syncthreads();
    float a = 0.f;
#pragma unroll 8
    for (int j = 0; j < D; j++) a += discW[t * D + j] * sm[j];
    ws[t] = a;
}

__device__ __forceinline__ float warp_dot128(const float4* __restrict__ a,
                                             const float4* __restrict__ b, int lane) {
    float4 x = a[lane], y = b[lane];
    float s = x.x * y.x + x.y * y.y + x.z * y.z + x.w * y.w;
#pragma unroll
    for (int o = 16; o; o >>= 1) s += __shfl_down_sync(0xffffffffu, s, o);
    return s;
}

__global__ void k_loss(const float4* __restrict__ pos, const float4* __restrict__ neg,
                       const float4* __restrict__ ws, float* __restrict__ loss) {
    int tid = blockIdx.x * blockDim.x + threadIdx.x;
    int e = tid >> 5;
    if (e >= 2 * N3) return;
    int lane = tid & 31;
    int strm = (e >= N3);
    int r = e - strm * N3;
    const float4* row = (strm ? neg : pos) + r * 32;
    float s = warp_dot128(row, ws, lane);
    if (lane == 0) {
        float xx = strm ? s : -s;
        float sp = fmaxf(xx, 0.f) + log1pf(expf(-fabsf(xx)));
        atomicAdd(&loss[strm], sp);
    }
}

__global__ void k_pred_out(const float4* __restrict__ z, const float4* __restrict__ w3,
                           const float* __restrict__ b3, float* __restrict__ out) {
    int tid = blockIdx.x * blockDim.x + threadIdx.x;
    int e = tid >> 5;
    if (e >= 2 * EPAIR) return;
    int lane = tid & 31;
    float s = warp_dot128(z + e * 32, w3, lane);
    if (lane == 0) out[e] = s + b3[0];
}

__global__ void k_final_loss(const float* __restrict__ loss, float* __restrict__ out) {
    out[0] = (loss[0] + loss[1]) * (1.0f / (float)N3);
}

// ---------------- host orchestration ----------------
extern "C" void kernel_launch(void* const* d_in, const int* in_sizes, int n_in,
                              void* d_out, int out_size) {
    const float* x      = (const float*)d_in[0];
    const int* srcs[3]  = {(const int*)d_in[1], (const int*)d_in[3], (const int*)d_in[5]};
    const int* dsts[3]  = {(const int*)d_in[2], (const int*)d_in[4], (const int*)d_in[6]};
    const int* perm     = (const int*)d_in[7];
    const int* pos_src  = (const int*)d_in[8];
    const int* pos_dst  = (const int*)d_in[9];
    const int* neg_src  = (const int*)d_in[10];
    const int* neg_dst  = (const int*)d_in[11];
    const float* Ws[3]  = {(const float*)d_in[12], (const float*)d_in[15], (const float*)d_in[18]};
    const float* Wn[3]  = {(const float*)d_in[13], (const float*)d_in[16], (const float*)d_in[19]};
    const float* bb[3]  = {(const float*)d_in[14], (const float*)d_in[17], (const float*)d_in[20]};
    const float* gamma[2] = {(const float*)d_in[21], (const float*)d_in[23]};
    const float* beta [2] = {(const float*)d_in[22], (const float*)d_in[24]};
    const float* discW  = (const float*)d_in[25];
    const float* pW1 = (const float*)d_in[26]; const float* pb1 = (const float*)d_in[27];
    const float* pW2 = (const float*)d_in[28]; const float* pb2 = (const float*)d_in[29];
    const float* pW3 = (const float*)d_in[30]; const float* pb3 = (const float*)d_in[31];
    float* out = (float*)d_out;

    int E[3] = {in_sizes[1], in_sizes[3], in_sizes[5]};
    int ND[3] = {N1, N2, N3};
    int segbase[3] = {0, N1, N1 + N2};

    float *p_xneg, *p_bufA, *p_bufB, *p_agg, *p_stats, *p_csum, *p_csq,
          *p_ws, *p_loss, *p_z, *p_z2;
    int *p_cnt, *p_off, *p_cur, *p_csr;
    cudaGetSymbolAddress((void**)&p_xneg,  g_xneg);
    cudaGetSymbolAddress((void**)&p_bufA,  g_bufA);
    cudaGetSymbolAddress((void**)&p_bufB,  g_bufB);
    cudaGetSymbolAddress((void**)&p_agg,   g_agg);
    cudaGetSymbolAddress((void**)&p_cnt,   g_cnt);
    cudaGetSymbolAddress((void**)&p_off,   g_off);
    cudaGetSymbolAddress((void**)&p_cur,   g_cur);
    cudaGetSymbolAddress((void**)&p_csr,   g_csr);
    cudaGetSymbolAddress((void**)&p_stats, g_stats);
    cudaGetSymbolAddress((void**)&p_csum,  g_csum);
    cudaGetSymbolAddress((void**)&p_csq,   g_csq_dummy);
    cudaGetSymbolAddress((void**)&p_ws,    g_ws);
    cudaGetSymbolAddress((void**)&p_loss,  g_loss);
    cudaGetSymbolAddress((void**)&p_z,     g_z);
    cudaGetSymbolAddress((void**)&p_z2,    g_z2);

    const size_t GEMM_SMEM = 131072;
    cudaFuncSetAttribute(gemm128_v2<true,  false>, cudaFuncAttributeMaxDynamicSharedMemorySize, GEMM_SMEM);
    cudaFuncSetAttribute(gemm128_v2<false, false>, cudaFuncAttributeMaxDynamicSharedMemorySize, GEMM_SMEM);
    cudaFuncSetAttribute(gemm128_v2<false, true >, cudaFuncAttributeMaxDynamicSharedMemorySize, GEMM_SMEM);

    int Etot = E[0] + E[1] + E[2];

    // negative-stream features
    k_gather_perm<<<(N0 * 32 + 255) / 256, 256>>>((const float4*)x, perm, (float4*)p_xneg);

    // batched CSR build
    cudaMemsetAsync(p_cnt, 0, NTOT * sizeof(int), 0);
    cudaMemsetAsync(p_cur, 0, NTOT * sizeof(int), 0);
    k_count_all<<<(Etot + 255) / 256, 256>>>(dsts[0], E[0], dsts[1], E[1], dsts[2], E[2], p_cnt);
    k_scan<<<1, 1024>>>(p_cnt, NTOT, p_off);
    k_fill_all<<<(Etot + 255) / 256, 256>>>(srcs[0], dsts[0], E[0],
                                            srcs[1], dsts[1], E[1],
                                            srcs[2], dsts[2], E[2],
                                            p_off, p_cur, p_csr);

    const float* hin[2] = {x, p_xneg};
    float* bufA[2] = {p_bufA, p_bufA + (size_t)N1 * D};
    float* bufB[2] = {p_bufB, p_bufB + (size_t)N2 * D};
    float* agg[2]  = {p_agg,  p_agg  + (size_t)N1 * D};

    for (int l = 0; l < 3; l++) {
        int nd = ND[l];
        float* outb[2];
        if (l == 1) { outb[0] = bufB[0]; outb[1] = bufB[1]; }
        else        { outb[0] = bufA[0]; outb[1] = bufA[1]; }

        k_gather<<<(nd * 32 + 255) / 256, 256>>>(
            (const float4*)hin[0], (const float4*)hin[1], p_csr, p_off + segbase[l],
            (float4*)agg[0], (float4*)agg[1], nd);

        // fused self+neigh GEMM, both streams in one launch
        dim3 grid((nd + 127) / 128, 2);
        gemm128_v2<true, false><<<grid, 512, GEMM_SMEM>>>(
            (const float4*)hin[0], (const float4*)hin[1],
            (const float4*)agg[0], (const float4*)agg[1],
            (const float4*)Ws[l], (const float4*)Wn[l], bb[l],
            (float4*)outb[0], (float4*)outb[1],
            nullptr, nullptr, nullptr, nullptr, nd, 0);

        if (l < 2) {
            for (int s = 0; s < 2; s++) {
                float* st_sum = p_stats + s * 2 * D;
                float* st_sq  = st_sum + D;
                cudaMemsetAsync(st_sum, 0, 2 * D * sizeof(float), 0);
                k_colstats<<<(nd + 255) / 256, 128>>>(outb[s], nd, st_sum, st_sq);
                k_bnrelu<<<(nd * D + 255) / 256, 256>>>(outb[s], st_sum, st_sq,
                                                        gamma[l], beta[l], nd);
            }
        }
        hin[0] = outb[0];
        hin[1] = outb[1];
    }

    float* positive = bufA[0];
    float* negative = bufA[1];

    cudaMemsetAsync(p_csum, 0, D * sizeof(float), 0);
    cudaMemsetAsync(p_loss, 0, 2 * sizeof(float), 0);
    k_colstats<<<(N3 + 255) / 256, 128>>>(positive, N3, p_csum, p_csq);
    k_summary_ws<<<1, 128>>>(p_csum, discW, p_ws);
    k_loss<<<(2 * N3 * 32 + 255) / 256, 256>>>((const float4*)positive,
                                               (const float4*)negative,
                                               (const float4*)p_ws, p_loss);

    // link predictor: 20000 rows (pos then neg); pair-product fused into GEMM1
    int Mp = 2 * EPAIR;
    dim3 pgrid((Mp + 127) / 128, 1);
    gemm128_v2<false, true><<<pgrid, 512, GEMM_SMEM>>>(
        (const float4*)positive, (const float4*)positive, nullptr, nullptr,
        (const float4*)pW1, nullptr, pb1, (float4*)p_z2, (float4*)p_z2,
        pos_src, pos_dst, neg_src, neg_dst, Mp, 1);
    gemm128_v2<false, false><<<pgrid, 512, GEMM_SMEM>>>(
        (const float4*)p_z2, (const float4*)p_z2, nullptr, nullptr,
        (const float4*)pW2, nullptr, pb2, (float4*)p_z, (float4*)p_z,
        nullptr, nullptr, nullptr, nullptr, Mp, 1);
    k_pred_out<<<(Mp * 32 + 255) / 256, 256>>>((const float4*)p_z,
                                               (const float4*)pW3, pb3, out);

    k_final_loss<<<1, 1>>>(p_loss, out + 2 * EPAIR);
}